// round 8
// baseline (speedup 1.0000x reference)
#include <cuda_runtime.h>
#include <cuda_fp16.h>
#include <cstdint>

#define DIM     64
#define KMAX    1024
#define TM      512
#define THREADS 512

// ---------------- device globals (prep results) ----------------
__device__ float g_c2[KMAX];
__device__ unsigned int g_cmaxU;   // asuint(max ||c_k||), positive-float monotone
// fp16 codebook scaled by 512, 128B rows, 16B-chunk XOR swizzle: chunk_phys = chunk ^ (k&7)
__device__ __align__(16) unsigned short g_cbH[KMAX * DIM];

// ---------------- smem layout (byte offsets) ----------------
#define OFF_CB    0          // 1024*128 = 131072
#define OFF_A     131072     // 512*128  =  65536
#define OFF_C2    196608     // 4096
#define OFF_C2B   200704     // 4096  (c2 + 0.25 bias)
#define OFF_R2    204800     // 2048
#define OFF_M1    206848     // 2048
#define OFF_M2    208896     // 2048
#define OFF_M3    210944     // 2048
#define OFF_FLAG  212992     // 2048
#define OFF_NF    215040     // 16
#define SMEM_DYN  215072

#define BIAS 0.25f
#define DEQ  (-0.00390625f)   // -2^-8 : undoes B x512 and applies the -2 factor

__device__ __forceinline__ uint32_t smem_u32(const void* p) {
    uint32_t a;
    asm("{ .reg .u64 t; cvta.to.shared.u64 t, %1; cvt.u32.u64 %0, t; }"
        : "=r"(a) : "l"(p));
    return a;
}

// ---------------- prep: c2 (R1-exact) + swizzled fp16 codebook (x512) + Cmax ----------------
__global__ void prep_kernel(const float* __restrict__ cb, int K) {
    int k = blockIdx.x * blockDim.x + threadIdx.x;
    if (k >= K) return;
    const float4* row = reinterpret_cast<const float4*>(cb + (size_t)k * DIM);
    float vals[DIM];
    float p0 = 0.f, p1 = 0.f, p2 = 0.f, p3 = 0.f;
#pragma unroll
    for (int j = 0; j < 16; j += 4) {
        float4 a = row[j + 0];
        float4 b = row[j + 1];
        float4 c = row[j + 2];
        float4 d = row[j + 3];
        p0 += a.x * a.x + a.y * a.y + a.z * a.z + a.w * a.w;
        p1 += b.x * b.x + b.y * b.y + b.z * b.z + b.w * b.w;
        p2 += c.x * c.x + c.y * c.y + c.z * c.z + c.w * c.w;
        p3 += d.x * d.x + d.y * d.y + d.z * d.z + d.w * d.w;
        vals[4*(j+0)+0]=a.x; vals[4*(j+0)+1]=a.y; vals[4*(j+0)+2]=a.z; vals[4*(j+0)+3]=a.w;
        vals[4*(j+1)+0]=b.x; vals[4*(j+1)+1]=b.y; vals[4*(j+1)+2]=b.z; vals[4*(j+1)+3]=b.w;
        vals[4*(j+2)+0]=c.x; vals[4*(j+2)+1]=c.y; vals[4*(j+2)+2]=c.z; vals[4*(j+2)+3]=c.w;
        vals[4*(j+3)+0]=d.x; vals[4*(j+3)+1]=d.y; vals[4*(j+3)+2]=d.z; vals[4*(j+3)+3]=d.w;
    }
    float c2 = (p0 + p1) + (p2 + p3);
    g_c2[k] = c2;
    atomicMax(&g_cmaxU, __float_as_uint(sqrtf(c2)));
#pragma unroll
    for (int c = 0; c < DIM; c++) {
        __half h = __float2half(vals[c] * 512.0f);   // x512 exact, one rn rounding
        int phys = (c >> 3) ^ (k & 7);               // 16B chunk swizzle
        g_cbH[(size_t)k * DIM + phys * 8 + (c & 7)] = *reinterpret_cast<unsigned short*>(&h);
    }
}

// ---------------- inner-step macros ----------------
#define MMAF16(d0, d1, d2, d3, ar, b0r, b1r)                                       \
    asm volatile(                                                                  \
        "mma.sync.aligned.m16n8k16.row.col.f32.f16.f16.f32 "                       \
        "{%0,%1,%2,%3}, {%4,%5,%6,%7}, {%8,%9}, {%0,%1,%2,%3};"                    \
        : "+f"(d0), "+f"(d1), "+f"(d2), "+f"(d3)                                   \
        : "r"((ar)[0]), "r"((ar)[1]), "r"((ar)[2]), "r"((ar)[3]),                  \
          "r"(b0r), "r"(b1r))

#define LDSM_X4(bq, off, addr)                                                     \
    asm volatile("ldmatrix.sync.aligned.m8n8.x4.shared.b16 {%0,%1,%2,%3}, [%4];"   \
        : "=r"((bq)[(off)]),   "=r"((bq)[(off)+1]),                                \
          "=r"((bq)[(off)+2]), "=r"((bq)[(off)+3]) : "r"(addr))

// insert packed value v into the sorted triple (M1,M2,M3)[slot]
#define MIN3(s, v) do {                                                            \
    unsigned int t1 = umax(M1[s], (v)); M1[s] = umin(M1[s], (v));                  \
    unsigned int t2 = umax(M2[s], t1);  M2[s] = umin(M2[s], t1);                   \
    M3[s] = umin(M3[s], t2);                                                       \
} while (0)

// pack: clear 10 mantissa LSBs, or in column index (s_b > 0 => asuint monotone)
#define PACKV(sv, col) ((__float_as_uint(sv) & 0xFFFFFC00u) | (unsigned int)(col))

// one n-tile: 8 fp16 MMAs (4 independent 2-chains), combine, encode, min3-insert
#define STEP(bq, ntv) do {                                                         \
    const float2 c2v = *reinterpret_cast<const float2*>(c2Bp + ((ntv) << 3));      \
    float e0 = 0.f, e1 = 0.f, e2 = 0.f, e3 = 0.f;                                  \
    float f0 = 0.f, f1 = 0.f, f2 = 0.f, f3 = 0.f;                                  \
    float g0 = 0.f, g1 = 0.f, g2 = 0.f, g3 = 0.f;                                  \
    float h0 = 0.f, h1 = 0.f, h2 = 0.f, h3 = 0.f;                                  \
    MMAF16(e0, e1, e2, e3, a[0][0], (bq)[0], (bq)[1]);                             \
    MMAF16(g0, g1, g2, g3, a[1][0], (bq)[0], (bq)[1]);                             \
    MMAF16(f0, f1, f2, f3, a[0][2], (bq)[4], (bq)[5]);                             \
    MMAF16(h0, h1, h2, h3, a[1][2], (bq)[4], (bq)[5]);                             \
    MMAF16(e0, e1, e2, e3, a[0][1], (bq)[2], (bq)[3]);                             \
    MMAF16(g0, g1, g2, g3, a[1][1], (bq)[2], (bq)[3]);                             \
    MMAF16(f0, f1, f2, f3, a[0][3], (bq)[6], (bq)[7]);                             \
    MMAF16(h0, h1, h2, h3, a[1][3], (bq)[6], (bq)[7]);                             \
    const int colb = ((ntv) << 3) + ((lane & 3) << 1);                             \
    float s;                                                                       \
    s = __fmaf_rn(__fadd_rn(e0, f0), DEQ, c2v.x); MIN3(0, PACKV(s, colb));         \
    s = __fmaf_rn(__fadd_rn(e1, f1), DEQ, c2v.y); MIN3(0, PACKV(s, colb + 1));     \
    s = __fmaf_rn(__fadd_rn(e2, f2), DEQ, c2v.x); MIN3(1, PACKV(s, colb));         \
    s = __fmaf_rn(__fadd_rn(e3, f3), DEQ, c2v.y); MIN3(1, PACKV(s, colb + 1));     \
    s = __fmaf_rn(__fadd_rn(g0, h0), DEQ, c2v.x); MIN3(2, PACKV(s, colb));         \
    s = __fmaf_rn(__fadd_rn(g1, h1), DEQ, c2v.y); MIN3(2, PACKV(s, colb + 1));     \
    s = __fmaf_rn(__fadd_rn(g2, h2), DEQ, c2v.x); MIN3(3, PACKV(s, colb));         \
    s = __fmaf_rn(__fadd_rn(g3, h3), DEQ, c2v.y); MIN3(3, PACKV(s, colb + 1));     \
} while (0)

// merge other sorted triple (o1<=o2<=o3) into (M1,M2,M3)[slot]
#define MERGE3(s, o1, o2, o3) do {                                                 \
    unsigned int z1 = umin(M1[s], (o1)), w1 = umax(M1[s], (o1));                   \
    unsigned int z2 = umin(M2[s], (o2)), w2 = umax(M2[s], (o2));                   \
    unsigned int z3 = umin(M3[s], (o3));                                           \
    M1[s] = z1;                                                                    \
    unsigned int q = umin(w1, z2);                                                 \
    M3[s] = umin(umax(w1, z2), umin(w2, z3));                                      \
    M2[s] = q;                                                                     \
} while (0)

// ---------------- main kernel ----------------
__global__ __launch_bounds__(THREADS, 1)
void vq_main(const float* __restrict__ residual,
             const float* __restrict__ cb,
             float* __restrict__ qout,
             float* __restrict__ codes,
             int N, int K, int wq, int wc)
{
    extern __shared__ __align__(16) unsigned char dsm[];
    const uint32_t sb = smem_u32(dsm);

    float*        sC2  = (float*)(dsm + OFF_C2);
    float*        sC2B = (float*)(dsm + OFF_C2B);
    float*        sR2  = (float*)(dsm + OFF_R2);
    unsigned int* sM1  = (unsigned int*)(dsm + OFF_M1);
    unsigned int* sM2  = (unsigned int*)(dsm + OFF_M2);
    unsigned int* sM3  = (unsigned int*)(dsm + OFF_M3);
    int*          sFlag= (int*)(dsm + OFF_FLAG);
    int*          sNF  = (int*)(dsm + OFF_NF);

    const int tid  = threadIdx.x;
    const int lane = tid & 31;
    const int warp = tid >> 5;
    const int m0   = blockIdx.x * TM;
    const int rows = (N - m0 < TM) ? (N - m0) : TM;
    const int NT   = K >> 3;

    if (tid == 0) *sNF = 0;

    // --- stage codebook image (pre-swizzled, identity uint4 copy) ---
    {
        const uint4* src = reinterpret_cast<const uint4*>(g_cbH);
        uint4* dst = reinterpret_cast<uint4*>(dsm + OFF_CB);
        const int n16 = (K * DIM * 2) / 16;
#pragma unroll 4
        for (int i = tid; i < n16; i += THREADS) dst[i] = src[i];
    }
    for (int i = tid; i < K; i += THREADS) {
        float c2 = g_c2[i];
        sC2[i]  = c2;
        sC2B[i] = c2 + BIAS;
    }

    // --- per-row: residual -> fp16 swizzled smem + exact r2 (R1 pattern) ---
    {
        const int r = tid;
        unsigned int* aU = reinterpret_cast<unsigned int*>(dsm + OFF_A) + r * 32;
        float r2 = 0.f;
        if (r < rows) {
            const float4* rr = reinterpret_cast<const float4*>(residual + (size_t)(m0 + r) * DIM);
            float p0 = 0.f, p1 = 0.f, p2 = 0.f, p3 = 0.f;
#pragma unroll
            for (int j = 0; j < 16; j++) {
                float4 v = rr[j];
                p0 += v.x * v.x;
                p1 += v.y * v.y;
                p2 += v.z * v.z;
                p3 += v.w * v.w;
                __half2 h0 = __floats2half2_rn(v.x, v.y);
                __half2 h1 = __floats2half2_rn(v.z, v.w);
                int j0 = 2 * j, j1 = 2 * j + 1;
                aU[(((j0 >> 2) ^ (r & 7)) << 2) + (j0 & 3)] = *reinterpret_cast<unsigned int*>(&h0);
                aU[(((j1 >> 2) ^ (r & 7)) << 2) + (j1 & 3)] = *reinterpret_cast<unsigned int*>(&h1);
            }
            r2 = (p0 + p1) + (p2 + p3);
        } else {
#pragma unroll
            for (int j = 0; j < 32; j++) aU[j] = 0;
        }
        sR2[r] = r2;
    }
    __syncthreads();

    // --- A fragments (resident): 2 m-tiles x 4 k-chunks, swizzled ldmatrix.x4 ---
    uint32_t a[2][4][4];
#pragma unroll
    for (int mt = 0; mt < 2; mt++) {
        const uint32_t rowb = (uint32_t)(warp * 32 + mt * 16 + (lane & 15)) * 128u;
#pragma unroll
        for (int kc = 0; kc < 4; kc++) {
            uint32_t phys = (uint32_t)((2 * kc + (lane >> 4)) ^ (lane & 7));
            uint32_t ad = sb + OFF_A + rowb + (phys << 4);
            asm volatile("ldmatrix.sync.aligned.m8n8.x4.shared.b16 {%0,%1,%2,%3}, [%4];"
                : "=r"(a[mt][kc][0]), "=r"(a[mt][kc][1]),
                  "=r"(a[mt][kc][2]), "=r"(a[mt][kc][3])
                : "r"(ad));
        }
    }

    // --- per-lane B base addresses (swizzled; +nt*1024 per tile) ---
    const uint32_t bb0 = sb + OFF_CB + (uint32_t)(lane & 7) * 128u
                       + ((uint32_t)(((lane >> 3))     ^ (lane & 7)) << 4);
    const uint32_t bb1 = sb + OFF_CB + (uint32_t)(lane & 7) * 128u
                       + ((uint32_t)((4 + (lane >> 3)) ^ (lane & 7)) << 4);
    const float* c2Bp = sC2B + ((lane & 3) << 1);

    // ================= single pass: packed min-3 of s_b = (c2+BIAS) - 2^-8*dot' =================
    unsigned int M1[4], M2[4], M3[4];
#pragma unroll
    for (int s = 0; s < 4; s++) { M1[s] = 0xFFFFFFFFu; M2[s] = 0xFFFFFFFFu; M3[s] = 0xFFFFFFFFu; }

    {
        uint32_t bc[8], bn[8];
        LDSM_X4(bc, 0, bb0);
        LDSM_X4(bc, 4, bb1);
        for (int nt = 0; nt < NT; nt += 2) {
            LDSM_X4(bn, 0, bb0 + (nt + 1) * 1024);
            LDSM_X4(bn, 4, bb1 + (nt + 1) * 1024);
            STEP(bc, nt);
            if (nt + 2 < NT) {
                LDSM_X4(bc, 0, bb0 + (nt + 2) * 1024);
                LDSM_X4(bc, 4, bb1 + (nt + 2) * 1024);
            }
            STEP(bn, nt + 1);
        }
    }

    // --- quad-merge min-3 across the 4 lanes covering each row ---
#pragma unroll
    for (int st = 1; st <= 2; st <<= 1) {
#pragma unroll
        for (int s = 0; s < 4; s++) {
            unsigned int o1 = __shfl_xor_sync(0xFFFFFFFFu, M1[s], st);
            unsigned int o2 = __shfl_xor_sync(0xFFFFFFFFu, M2[s], st);
            unsigned int o3 = __shfl_xor_sync(0xFFFFFFFFu, M3[s], st);
            MERGE3(s, o1, o2, o3);
        }
    }
    {
        const int rbase = warp * 32 + (lane >> 2);
        if ((lane & 3) == 0) {
#pragma unroll
            for (int s = 0; s < 4; s++) {
                int row = rbase + s * 8;
                sM1[row] = M1[s]; sM2[row] = M2[s]; sM3[row] = M3[s];
            }
        }
    }
    __syncthreads();

    // ================= per-row decision =================
    const float CmaxC = __uint_as_float(g_cmaxU) * 0.00390625f;   // Cmax * 2^-8
    const int t = tid;
    if (t < rows) {
        const unsigned int u1 = sM1[t], u2 = sM2[t], u3 = sM3[t];
        const float f1 = __uint_as_float(u1 & 0xFFFFFC00u);
        const float f2 = __uint_as_float(u2 & 0xFFFFFC00u);
        const float f3 = __uint_as_float(u3 & 0xFFFFFC00u);
        const float r2 = sR2[t];
        const float th = sqrtf(r2) * CmaxC + 1e-4f;
        int bestK = -1;
        if (f2 - f1 > th) {
            bestK = (int)(u1 & 1023u);               // unique in window => argmin
        } else if (f3 - f1 > th) {
            // exactly 2 candidates: exact fp32 recheck (R1 math, lexicographic)
            const int k1 = (int)(u1 & 1023u), k2 = (int)(u2 & 1023u);
            const float4* rr = reinterpret_cast<const float4*>(residual + (size_t)(m0 + t) * DIM);
            const float4* c1 = reinterpret_cast<const float4*>(cb + (size_t)k1 * DIM);
            const float4* c2r = reinterpret_cast<const float4*>(cb + (size_t)k2 * DIM);
            float a1 = 0.f, a2 = 0.f;
#pragma unroll
            for (int j = 0; j < 16; j++) {
                float4 rv = rr[j];
                float4 v1 = c1[j];
                float4 v2 = c2r[j];
                a1 += rv.x * v1.x; a1 += rv.y * v1.y; a1 += rv.z * v1.z; a1 += rv.w * v1.w;
                a2 += rv.x * v2.x; a2 += rv.y * v2.y; a2 += rv.z * v2.z; a2 += rv.w * v2.w;
            }
            float d1 = (r2 + sC2[k1]) - 2.0f * a1;
            float d2 = (r2 + sC2[k2]) - 2.0f * a2;
            bestK = (d2 < d1 || (d2 == d1 && k2 < k1)) ? k2 : k1;
        } else {
            int idx = atomicAdd(sNF, 1);
            sFlag[idx] = t;
        }
        if (bestK >= 0) {
            const int n = m0 + t;
            if (wc) codes[n] = (float)bestK;
            if (wq) {
                const float4* brow = reinterpret_cast<const float4*>(cb + (size_t)bestK * DIM);
                float4* qo = reinterpret_cast<float4*>(qout + (size_t)n * DIM);
#pragma unroll
                for (int j = 0; j < 16; j++) qo[j] = brow[j];
            }
        }
    }
    __syncthreads();

    // ================= cooperative exact rescan for flagged rows (rare) =================
    const int nf = *sNF;
    for (int i = warp; i < nf; i += 16) {
        const int row = sFlag[i];
        const int n = m0 + row;
        const float r2 = sR2[row];
        float r[DIM];
        {
            const float4* rr = reinterpret_cast<const float4*>(residual + (size_t)n * DIM);
#pragma unroll
            for (int j = 0; j < 16; j++) {
                float4 v = rr[j];
                r[4 * j + 0] = v.x; r[4 * j + 1] = v.y;
                r[4 * j + 2] = v.z; r[4 * j + 3] = v.w;
            }
        }
        float best = 3.402823466e+38f;
        int bestK = 0x7FFFFFFF;
        for (int k = lane; k < K; k += 32) {
            const float4* c4 = reinterpret_cast<const float4*>(cb + (size_t)k * DIM);
            float a0 = 0.f;
#pragma unroll
            for (int j = 0; j < 16; j++) {
                float4 v = c4[j];
                a0 += r[4 * j + 0] * v.x;
                a0 += r[4 * j + 1] * v.y;
                a0 += r[4 * j + 2] * v.z;
                a0 += r[4 * j + 3] * v.w;
            }
            float d = (r2 + sC2[k]) - 2.0f * a0;
            if (d < best || (d == best && k < bestK)) { best = d; bestK = k; }
        }
#pragma unroll
        for (int off = 16; off >= 1; off >>= 1) {
            float ob = __shfl_xor_sync(0xFFFFFFFFu, best, off);
            int   ok = __shfl_xor_sync(0xFFFFFFFFu, bestK, off);
            if (ob < best || (ob == best && ok < bestK)) { best = ob; bestK = ok; }
        }
        if (wc && lane == 0) codes[n] = (float)bestK;
        if (wq && lane < 16) {
            const float4* brow = reinterpret_cast<const float4*>(cb + (size_t)bestK * DIM);
            reinterpret_cast<float4*>(qout + (size_t)n * DIM)[lane] = brow[lane];
        }
    }
}

// ---------------- launch ----------------
extern "C" void kernel_launch(void* const* d_in, const int* in_sizes, int n_in,
                              void* d_out, int out_size)
{
    const float* residual = (const float*)d_in[0];
    const float* cb       = (const float*)d_in[1];
    const int N = in_sizes[0] / DIM;
    const int K = in_sizes[1] / DIM;

    float* out = (float*)d_out;
    int write_q = 0, write_codes = 0;
    float* qout = out;
    float* codes = out;
    if (out_size >= N * DIM + N) {
        write_q = 1; write_codes = 1;
        codes = out + (size_t)N * DIM;
    } else if (out_size >= N * DIM) {
        write_q = 1;
    } else {
        write_codes = 1;
    }

    cudaFuncSetAttribute(vq_main, cudaFuncAttributeMaxDynamicSharedMemorySize, SMEM_DYN);

    prep_kernel<<<(K + 255) / 256, 256>>>(cb, K);

    int blocks = (N + TM - 1) / TM;
    vq_main<<<blocks, THREADS, SMEM_DYN>>>(residual, cb, qout, codes,
                                           N, K, write_q, write_codes);
}

// round 9
// speedup vs baseline: 1.3535x; 1.3535x over previous
#include <cuda_runtime.h>
#include <cuda_bf16.h>
#include <cstdint>

#define DIM     64
#define KMAX    1024
#define TM      256          // rows per CTA
#define THREADS 512          // 16 warps, 1 m-tile (16 rows) each
#define CAP     16

// ---------------- device globals (prep results) ----------------
__device__ float g_c2[KMAX];
__device__ unsigned int g_cmaxU;   // asuint(max ||c_k||), positive-float monotone
// fragment-ordered bf16 codebook image: for each n-tile (8 codes) the exact
// 8 B-fragment regs x 32 lanes the MMA needs. uint4 index = nt*64 + half*32 + lane.
__device__ __align__(16) uint4 g_cbFrag[(KMAX / 8) * 64];

// ---------------- smem layout (byte offsets) ----------------
#define OFF_A     0          // 256*128 = 32768 (bf16 swizzled A staging)
#define OFF_C2    32768      // 1024*4  =  4096
#define OFF_R2    36864      // 256*4   =  1024
#define OFF_CNT   37888      // 256*4   =  1024
#define OFF_CAND  38912      // 256*16*2 = 8192
#define SMEM_DYN  47104

__device__ __forceinline__ uint32_t smem_u32(const void* p) {
    uint32_t a;
    asm("{ .reg .u64 t; cvta.to.shared.u64 t, %1; cvt.u32.u64 %0, t; }"
        : "=r"(a) : "l"(p));
    return a;
}

// ---------------- prep: c2 (R1-exact) + fragment-ordered bf16 codebook + Cmax ----------------
__global__ void prep_kernel(const float* __restrict__ cb, int K) {
    int k = blockIdx.x * blockDim.x + threadIdx.x;
    if (k >= K) return;
    const float4* row = reinterpret_cast<const float4*>(cb + (size_t)k * DIM);
    float vals[DIM];
    float p0 = 0.f, p1 = 0.f, p2 = 0.f, p3 = 0.f;
#pragma unroll
    for (int j = 0; j < 16; j += 4) {
        float4 a = row[j + 0];
        float4 b = row[j + 1];
        float4 c = row[j + 2];
        float4 d = row[j + 3];
        p0 += a.x * a.x + a.y * a.y + a.z * a.z + a.w * a.w;
        p1 += b.x * b.x + b.y * b.y + b.z * b.z + b.w * b.w;
        p2 += c.x * c.x + c.y * c.y + c.z * c.z + c.w * c.w;
        p3 += d.x * d.x + d.y * d.y + d.z * d.z + d.w * d.w;
        vals[4*(j+0)+0]=a.x; vals[4*(j+0)+1]=a.y; vals[4*(j+0)+2]=a.z; vals[4*(j+0)+3]=a.w;
        vals[4*(j+1)+0]=b.x; vals[4*(j+1)+1]=b.y; vals[4*(j+1)+2]=b.z; vals[4*(j+1)+3]=b.w;
        vals[4*(j+2)+0]=c.x; vals[4*(j+2)+1]=c.y; vals[4*(j+2)+2]=c.z; vals[4*(j+2)+3]=c.w;
        vals[4*(j+3)+0]=d.x; vals[4*(j+3)+1]=d.y; vals[4*(j+3)+2]=d.z; vals[4*(j+3)+3]=d.w;
    }
    float c2 = (p0 + p1) + (p2 + p3);
    g_c2[k] = c2;
    atomicMax(&g_cmaxU, __float_as_uint(sqrtf(c2)));

    // Fragment image: lane l=4*i+q (i = code-in-tile) receives in b-reg j the bf16
    // pair (k-dims 8j+2q, 8j+2q+1). uint addr = nt*256 + (j>>2)*128 + l*4 + (j&3).
    const int nt = k >> 3, i = k & 7;
    unsigned int* frag = reinterpret_cast<unsigned int*>(g_cbFrag) + nt * 256;
#pragma unroll
    for (int j = 0; j < 8; j++) {
#pragma unroll
        for (int q = 0; q < 4; q++) {
            __nv_bfloat162 pr = __floats2bfloat162_rn(vals[8 * j + 2 * q],
                                                      vals[8 * j + 2 * q + 1]);
            frag[(j >> 2) * 128 + (4 * i + q) * 4 + (j & 3)] =
                *reinterpret_cast<unsigned int*>(&pr);
        }
    }
}

// ---------------- inner-step macros ----------------
#define MMA16816(d0, d1, d2, d3, ar, b0r, b1r)                                    \
    asm volatile(                                                                  \
        "mma.sync.aligned.m16n8k16.row.col.f32.bf16.bf16.f32 "                     \
        "{%0,%1,%2,%3}, {%4,%5,%6,%7}, {%8,%9}, {%0,%1,%2,%3};"                    \
        : "+f"(d0), "+f"(d1), "+f"(d2), "+f"(d3)                                   \
        : "r"((ar)[0]), "r"((ar)[1]), "r"((ar)[2]), "r"((ar)[3]),                  \
          "r"(b0r), "r"(b1r))

// one n-tile: 4 MMAs (2 independent chains), combine, produce s0..s3
#define COMPUTE_S(bc0, bc1, ntv)                                                   \
    const float2 c2v = *reinterpret_cast<const float2*>(c2p + ((ntv) << 3));       \
    float s0, s1, s2, s3;                                                          \
    {                                                                              \
        float e0 = 0.f, e1 = 0.f, e2 = 0.f, e3 = 0.f;                              \
        float f0 = 0.f, f1 = 0.f, f2 = 0.f, f3 = 0.f;                              \
        MMA16816(e0, e1, e2, e3, a[0], (bc0).x, (bc0).y);                          \
        MMA16816(f0, f1, f2, f3, a[2], (bc1).x, (bc1).y);                          \
        MMA16816(e0, e1, e2, e3, a[1], (bc0).z, (bc0).w);                          \
        MMA16816(f0, f1, f2, f3, a[3], (bc1).z, (bc1).w);                          \
        s0 = __fmaf_rn(__fadd_rn(e0, f0), -2.0f, c2v.x);                           \
        s1 = __fmaf_rn(__fadd_rn(e1, f1), -2.0f, c2v.y);                           \
        s2 = __fmaf_rn(__fadd_rn(e2, f2), -2.0f, c2v.x);                           \
        s3 = __fmaf_rn(__fadd_rn(e3, f3), -2.0f, c2v.y);                           \
    }

#define APPEND(rr, kk) do {                                                        \
    int c = atomicAdd(&sCNT[(rr)], 1);                                             \
    if (c < CAP) sCand[(rr) * CAP + c] = (unsigned short)(kk);                     \
} while (0)

// ---------------- main: two-pass HMMA, B streamed from L1/L2 as raw fragments ----------------
__global__ __launch_bounds__(THREADS, 2)
void vq_main(const float* __restrict__ residual,
             const float* __restrict__ cb,
             float* __restrict__ qout,
             float* __restrict__ codes,
             int N, int K, int wq, int wc)
{
    extern __shared__ __align__(16) unsigned char dsm[];
    const uint32_t sb = smem_u32(dsm);

    float*          sC2   = (float*)(dsm + OFF_C2);
    float*          sR2   = (float*)(dsm + OFF_R2);
    int*            sCNT  = (int*)(dsm + OFF_CNT);
    unsigned short* sCand = (unsigned short*)(dsm + OFF_CAND);

    const int tid  = threadIdx.x;
    const int lane = tid & 31;
    const int warp = tid >> 5;
    const int m0   = blockIdx.x * TM;
    const int rows = (N - m0 < TM) ? (N - m0) : TM;
    const int NT   = K >> 3;

    for (int i = tid; i < K; i += THREADS) sC2[i] = g_c2[i];

    // --- per-row: residual -> bf16 swizzled smem + exact r2 (R1 pattern) ---
    if (tid < TM) {
        const int r = tid;
        unsigned int* aU = reinterpret_cast<unsigned int*>(dsm + OFF_A) + r * 32;
        float r2 = 0.f;
        if (r < rows) {
            const float4* rr = reinterpret_cast<const float4*>(residual + (size_t)(m0 + r) * DIM);
            float p0 = 0.f, p1 = 0.f, p2 = 0.f, p3 = 0.f;
#pragma unroll
            for (int j = 0; j < 16; j++) {
                float4 v = rr[j];
                p0 += v.x * v.x;
                p1 += v.y * v.y;
                p2 += v.z * v.z;
                p3 += v.w * v.w;
                __nv_bfloat162 h0 = __floats2bfloat162_rn(v.x, v.y);
                __nv_bfloat162 h1 = __floats2bfloat162_rn(v.z, v.w);
                int j0 = 2 * j, j1 = 2 * j + 1;
                aU[(((j0 >> 2) ^ (r & 7)) << 2) + (j0 & 3)] = *reinterpret_cast<unsigned int*>(&h0);
                aU[(((j1 >> 2) ^ (r & 7)) << 2) + (j1 & 3)] = *reinterpret_cast<unsigned int*>(&h1);
            }
            r2 = (p0 + p1) + (p2 + p3);
        } else {
#pragma unroll
            for (int j = 0; j < 32; j++) aU[j] = 0;
        }
        sR2[r]  = r2;
        sCNT[r] = 0;
    }
    __syncthreads();

    // --- A fragments (resident): 1 m-tile x 4 k-chunks, swizzled ldmatrix.x4 ---
    uint32_t a[4][4];
    {
        const uint32_t rowb = (uint32_t)(warp * 16 + (lane & 15)) * 128u;
#pragma unroll
        for (int kc = 0; kc < 4; kc++) {
            uint32_t phys = (uint32_t)((2 * kc + (lane >> 4)) ^ (lane & 7));
            uint32_t ad = sb + OFF_A + rowb + (phys << 4);
            asm volatile("ldmatrix.sync.aligned.m8n8.x4.shared.b16 {%0,%1,%2,%3}, [%4];"
                : "=r"(a[kc][0]), "=r"(a[kc][1]), "=r"(a[kc][2]), "=r"(a[kc][3])
                : "r"(ad));
        }
    }

    const uint4* bp = g_cbFrag + lane;          // per-lane fragment stream
    const float* c2p = sC2 + ((lane & 3) << 1);
    const int rA0 = warp * 16 + (lane >> 2);    // slot rows: rA0 and rA0+8

    // ================= PASS A: per-row min of s~ = c2 - 2*dot~ =================
    float m0a = 3.0e38f, m0b = 3.0e38f, m1a = 3.0e38f, m1b = 3.0e38f;
    {
        uint4 c0 = bp[0], c1 = bp[32];
        for (int nt = 0; nt < NT; nt++) {
            const int ntn = (nt + 1 < NT) ? nt + 1 : nt;
            uint4 n0 = bp[ntn * 64], n1 = bp[ntn * 64 + 32];
            COMPUTE_S(c0, c1, nt)
            m0a = fminf(m0a, s0); m0b = fminf(m0b, s1);
            m1a = fminf(m1a, s2); m1b = fminf(m1b, s3);
            c0 = n0; c1 = n1;
        }
    }

    // --- quad reduce + threshold -> per-slot limits ---
    const float CmaxC = __uint_as_float(g_cmaxU) * 0.018f;
    float lim0, lim1;
    {
        float v0 = fminf(m0a, m0b);
        float v1 = fminf(m1a, m1b);
        v0 = fminf(v0, __shfl_xor_sync(0xFFFFFFFFu, v0, 1));
        v0 = fminf(v0, __shfl_xor_sync(0xFFFFFFFFu, v0, 2));
        v1 = fminf(v1, __shfl_xor_sync(0xFFFFFFFFu, v1, 1));
        v1 = fminf(v1, __shfl_xor_sync(0xFFFFFFFFu, v1, 2));
        lim0 = v0 + (sqrtf(sR2[rA0])     * CmaxC + 5e-5f);
        lim1 = v1 + (sqrtf(sR2[rA0 + 8]) * CmaxC + 5e-5f);
    }

    // ================= PASS B: bitwise replay, collect s~ <= lim =================
    {
        uint4 c0 = bp[0], c1 = bp[32];
        for (int nt = 0; nt < NT; nt++) {
            const int ntn = (nt + 1 < NT) ? nt + 1 : nt;
            uint4 n0 = bp[ntn * 64], n1 = bp[ntn * 64 + 32];
            COMPUTE_S(c0, c1, nt)
            const int colb = (nt << 3) + ((lane & 3) << 1);
            if (fminf(s0, s1) <= lim0) {
                if (s0 <= lim0) APPEND(rA0, colb);
                if (s1 <= lim0) APPEND(rA0, colb + 1);
            }
            if (fminf(s2, s3) <= lim1) {
                if (s2 <= lim1) APPEND(rA0 + 8, colb);
                if (s3 <= lim1) APPEND(rA0 + 8, colb + 1);
            }
            c0 = n0; c1 = n1;
        }
    }
    __syncthreads();

    // ================= exact phase: R1-proven fp32 on candidate set =================
    const int t = tid;
    if (t < rows) {
        const int cn = sCNT[t];
        int bestK;
        if (cn == 1) {
            bestK = sCand[t * CAP];          // unique candidate: must be the argmin
        } else {
            const float r2 = sR2[t];
            float r[DIM];
            const float4* rr = reinterpret_cast<const float4*>(residual + (size_t)(m0 + t) * DIM);
#pragma unroll
            for (int j = 0; j < 16; j++) {
                float4 v = rr[j];
                r[4 * j + 0] = v.x; r[4 * j + 1] = v.y;
                r[4 * j + 2] = v.z; r[4 * j + 3] = v.w;
            }
            float best = 3.402823466e+38f;
            bestK = 0x7FFFFFFF;
            if (cn <= CAP) {
                for (int i = 0; i < cn; i++) {
                    int k = sCand[t * CAP + i];
                    const float4* c4 = reinterpret_cast<const float4*>(cb + (size_t)k * DIM);
                    float a0 = 0.f;
#pragma unroll
                    for (int j = 0; j < 16; j++) {
                        float4 v = c4[j];
                        a0 += r[4 * j + 0] * v.x;
                        a0 += r[4 * j + 1] * v.y;
                        a0 += r[4 * j + 2] * v.z;
                        a0 += r[4 * j + 3] * v.w;
                    }
                    float d = (r2 + sC2[k]) - 2.0f * a0;
                    if (d < best || (d == best && k < bestK)) { best = d; bestK = k; }
                }
            } else {
                for (int k = 0; k < K; k++) {      // overflow fallback (statistically never)
                    const float4* c4 = reinterpret_cast<const float4*>(cb + (size_t)k * DIM);
                    float a0 = 0.f;
#pragma unroll
                    for (int j = 0; j < 16; j++) {
                        float4 v = c4[j];
                        a0 += r[4 * j + 0] * v.x;
                        a0 += r[4 * j + 1] * v.y;
                        a0 += r[4 * j + 2] * v.z;
                        a0 += r[4 * j + 3] * v.w;
                    }
                    float d = (r2 + sC2[k]) - 2.0f * a0;
                    if (d < best) { best = d; bestK = k; }
                }
            }
        }
        const int n = m0 + t;
        if (wc) codes[n] = (float)bestK;
        if (wq) {
            const float4* brow = reinterpret_cast<const float4*>(cb + (size_t)bestK * DIM);
            float4* qo = reinterpret_cast<float4*>(qout + (size_t)n * DIM);
#pragma unroll
            for (int j = 0; j < 16; j++) qo[j] = brow[j];
        }
    }
}

// ---------------- launch ----------------
extern "C" void kernel_launch(void* const* d_in, const int* in_sizes, int n_in,
                              void* d_out, int out_size)
{
    const float* residual = (const float*)d_in[0];
    const float* cb       = (const float*)d_in[1];
    const int N = in_sizes[0] / DIM;
    const int K = in_sizes[1] / DIM;

    float* out = (float*)d_out;
    int write_q = 0, write_codes = 0;
    float* qout = out;
    float* codes = out;
    if (out_size >= N * DIM + N) {
        write_q = 1; write_codes = 1;
        codes = out + (size_t)N * DIM;
    } else if (out_size >= N * DIM) {
        write_q = 1;
    } else {
        write_codes = 1;
    }

    cudaFuncSetAttribute(vq_main, cudaFuncAttributeMaxDynamicSharedMemorySize, SMEM_DYN);

    prep_kernel<<<(K + 255) / 256, 256>>>(cb, K);

    int blocks = (N + TM - 1) / TM;
    vq_main<<<blocks, THREADS, SMEM_DYN>>>(residual, cb, qout, codes,
                                           N, K, write_q, write_codes);
}